// round 11
// baseline (speedup 1.0000x reference)
#include <cuda_runtime.h>
#include <math.h>

#define FULLMASK 0xffffffffu

constexpr int N_ = 50000;
constexpr int E_ = 400000;
constexpr int R_ = 4;
constexpr int HC_ = 128;   // H*C
constexpr int D_ = 64;     // IN == HID
constexpr int L_ = 2;
constexpr int K1_ = D_ + R_ * HC_;  // 576
constexpr int SEG_ = R_ * N_;       // 200000 segments
constexpr int CAP_ = 32;            // ELL capacity (deg ~ Poisson(4); P(>=32) ~ 1e-19)

// ---------------- scratch (device globals) ---------------------------------
__device__ int g_ellcnt[SEG_];          // zero-init at load; re-zeroed by setup
__device__ int g_ell[CAP_][SEG_];       // transposed ELL adjacency

__device__ float g_es[R_][N_][2];       // per-node source logits, per head
__device__ float g_ed[R_][N_][2];       // per-node dest logits, per head
__device__ float g_aggx[R_][N_][HC_];   // normalized alpha-weighted x, [h*64+k]
__device__ float g_hbuf[N_][D_];        // inter-layer features
__device__ float g_va[L_][2][R_][2][D_];  // folded W@a_{src,dst}
__device__ float g_W1f[L_][K1_][D_];    // MLP W1 with GAT W folded in
__device__ float g_b1f[L_][D_];         // b1 with gat_bias folded in

__device__ __forceinline__ float lrelu(float x) { return x > 0.f ? x : 0.2f * x; }

// packed 2xfp32 FMA (sm_100+): d = a*b + d elementwise on {lo,hi}
__device__ __forceinline__ void ffma2(unsigned long long& d,
                                      unsigned long long a, unsigned long long b) {
    asm("fma.rn.f32x2 %0, %1, %2, %3;" : "=l"(d) : "l"(a), "l"(b), "l"(d));
}
// duplicate a float into both halves of a packed f32x2
__device__ __forceinline__ unsigned long long packdup(float a) {
    unsigned long long d;
    unsigned int u = __float_as_uint(a);
    asm("mov.b64 %0, {%1, %1};" : "=l"(d) : "r"(u));
    return d;
}

// ================= merged one-time setup ====================================
// block 0: fold va; blocks 1..2: W1 head + b1; blocks 3..18: W1 body;
// blocks 19..: zero g_ellcnt (needed every replay)
__global__ __launch_bounds__(256) void setup_kernel(
    const float* __restrict__ gatW, const float* __restrict__ asrc,
    const float* __restrict__ adst, const float* __restrict__ W1,
    const float* __restrict__ b1, const float* __restrict__ gbias)
{
    __shared__ float Wt[64][65];   // [k][c]
    __shared__ float W1t[64][64];  // [c][j]
    int b = blockIdx.x;
    int tid = threadIdx.x;

    if (b == 0) {
#pragma unroll
        for (int it = 0; it < 4; it++) {
            int t = tid + it * 256;
            int k = t & 63;
            int h = (t >> 6) & 1;
            int r = (t >> 7) & 3;
            int l = t >> 9;
            const float* Wrow = gatW + (((size_t)(l * R_ + r) * 64 + k) * 128) + h * 64;
            const float* as = asrc + ((l * R_ + r) * 2 + h) * 64;
            const float* ad = adst + ((l * R_ + r) * 2 + h) * 64;
            float ss = 0.f, ds = 0.f;
#pragma unroll 16
            for (int c = 0; c < 64; c++) { ss += Wrow[c] * as[c]; ds += Wrow[c] * ad[c]; }
            g_va[l][0][r][h][k] = ss;
            g_va[l][1][r][h][k] = ds;
        }
    } else if (b <= L_) {
        int l = b - 1;
        for (int i = tid; i < 64 * 64 / 4; i += 256)
            ((float4*)&g_W1f[l][0][0])[i] = ((const float4*)&W1[(size_t)l * K1_ * 64])[i];
        if (tid < 64) {
            float bb = b1[l * 64 + tid];
            for (int row = 0; row < 512; row++) {
                int r = row >> 7, idx = row & 127;
                bb += gbias[(l * R_ + r) * HC_ + idx] *
                      W1[((size_t)l * K1_ + 64 + row) * 64 + tid];
            }
            g_b1f[l][tid] = bb;
        }
    } else if (b <= L_ + 16) {
        int sub = b - 3;
        int l = sub >> 3, r = (sub >> 1) & 3, h = sub & 1;
#pragma unroll
        for (int i = 0; i < 4; i++) {
            int s = tid + i * 256;
            int k = s >> 4, c4 = (s & 15) * 4;
            float4 wv = *(const float4*)&gatW[((size_t)(l * R_ + r) * 64 + k) * 128 + h * 64 + c4];
            Wt[k][c4] = wv.x; Wt[k][c4 + 1] = wv.y; Wt[k][c4 + 2] = wv.z; Wt[k][c4 + 3] = wv.w;
            int c = s >> 4, j4 = (s & 15) * 4;
            *(float4*)&W1t[c][j4] =
                *(const float4*)&W1[((size_t)l * K1_ + 64 + r * 128 + h * 64 + c) * 64 + j4];
        }
        __syncthreads();
        int j4 = (tid & 15) * 4;
        int kb = tid >> 4;
#pragma unroll
        for (int kk = 0; kk < 4; kk++) {
            int k = kb + kk * 16;
            float a0 = 0.f, a1 = 0.f, a2 = 0.f, a3 = 0.f;
#pragma unroll 16
            for (int c = 0; c < 64; c++) {
                float a = Wt[k][c];
                float4 wv = *(float4*)&W1t[c][j4];
                a0 += a * wv.x; a1 += a * wv.y; a2 += a * wv.z; a3 += a * wv.w;
            }
            *(float4*)&g_W1f[l][64 + r * 128 + h * 64 + k][j4] = make_float4(a0, a1, a2, a3);
        }
    } else {
        int i4 = (b - (L_ + 17)) * 256 + tid;
        if (i4 < SEG_ / 4) ((int4*)g_ellcnt)[i4] = make_int4(0, 0, 0, 0);
    }
}

// ================= ELL adjacency build (single kernel, no scan) ============
__global__ void ell_build_kernel(const int* __restrict__ ei, const float* __restrict__ ew) {
    int e = blockIdx.x * blockDim.x + threadIdx.x;
    if (e >= E_) return;
    float w = ew[e];
    if (w == 0.f) return;
    int s = ei[e], d = ei[E_ + e];
    int rf = (w > 0.f) ? 0 : 2;
    int seg0 = rf * N_ + d;
    int p0 = atomicAdd(&g_ellcnt[seg0], 1);
    if (p0 < CAP_) g_ell[p0][seg0] = s;
    int seg1 = (rf + 1) * N_ + s;
    int p1 = atomicAdd(&g_ellcnt[seg1], 1);
    if (p1 < CAP_) g_ell[p1][seg1] = d;
}

// ================= per-layer: logits (v2: hoisted va, float4 LDS) ==========
__global__ __launch_bounds__(256) void logits_kernel(const float* __restrict__ xin, int layer)
{
    __shared__ float xs[64][68];    // stride 68: 16B-aligned float4 rows
    __shared__ float vas[16][68];
    int tid = threadIdx.x;
    const float* xcur = layer ? &g_hbuf[0][0] : xin;
    int nb = blockIdx.x * 64;
#pragma unroll
    for (int i = 0; i < 4; i++) {
        int s = tid + i * 256;
        int row = s >> 4, c4 = (s & 15) * 4;
        int n = nb + row;
        float4 v = (n < N_) ? *(const float4*)&xcur[(size_t)n * 64 + c4]
                            : make_float4(0.f, 0.f, 0.f, 0.f);
        xs[row][c4] = v.x; xs[row][c4 + 1] = v.y; xs[row][c4 + 2] = v.z; xs[row][c4 + 3] = v.w;
    }
    {
        int o = tid >> 4, c4 = (tid & 15) * 4;
        int which = o >> 3, oo = o & 7;
        int r = oo >> 1, h = oo & 1;
        float4 v = *(const float4*)&g_va[layer][which][r][h][c4];
        vas[o][c4] = v.x; vas[o][c4 + 1] = v.y; vas[o][c4 + 2] = v.z; vas[o][c4 + 3] = v.w;
    }
    __syncthreads();

    int o = tid & 15;        // same output slot for all 4 nodes of this thread
    int n0 = tid >> 4;       // 0..15
    float s0 = 0.f, s1 = 0.f, s2 = 0.f, s3 = 0.f;
#pragma unroll
    for (int k4 = 0; k4 < 64; k4 += 4) {
        float4 va = *(float4*)&vas[o][k4];
        float4 a = *(float4*)&xs[n0][k4];
        float4 b = *(float4*)&xs[n0 + 16][k4];
        float4 c = *(float4*)&xs[n0 + 32][k4];
        float4 d = *(float4*)&xs[n0 + 48][k4];
        s0 += a.x * va.x + a.y * va.y + a.z * va.z + a.w * va.w;
        s1 += b.x * va.x + b.y * va.y + b.z * va.z + b.w * va.w;
        s2 += c.x * va.x + c.y * va.y + c.z * va.z + c.w * va.w;
        s3 += d.x * va.x + d.y * va.y + d.z * va.z + d.w * va.w;
    }
    int which = o >> 3, oo = o & 7;
    int r = oo >> 1, h = oo & 1;
    float sv[4] = {s0, s1, s2, s3};
#pragma unroll
    for (int i = 0; i < 4; i++) {
        int n = nb + n0 + i * 16;
        if (n < N_) {
            if (which == 0) g_es[r][n][h] = sv[i];
            else            g_ed[r][n][h] = sv[i];
        }
    }
}

// ================= per-layer: ELL softmax-aggregate ========================
// 4 segments per warp, 8 lanes per segment; warp-uniform loop with a true
// branch guard so inactive octets issue NO loads. Transposed ELL makes the
// per-iteration neighbor fetch one coalesced 16B load per warp.
__global__ __launch_bounds__(256) void agg_kernel(const float* __restrict__ xin, int layer)
{
    const float* xcur = layer ? &g_hbuf[0][0] : xin;
    int warp = (blockIdx.x * 256 + threadIdx.x) >> 5;
    int lane = threadIdx.x & 31;
    int li = lane & 7;
    int seg = warp * 4 + (lane >> 3);   // SEG_ % 4 == 0
    if (seg >= SEG_) return;
    int r = seg / N_;
    int n = seg - r * N_;

    int deg = __ldg(&g_ellcnt[seg]);
    deg = deg < CAP_ ? deg : CAP_;

    float2 ed2 = *(const float2*)&g_ed[r][n][0];
    float2 es2 = *(const float2*)&g_es[r][n][0];
    float p0 = __expf(lrelu(es2.x + ed2.x));   // self loop, head 0
    float p1 = __expf(lrelu(es2.y + ed2.y));   // self loop, head 1
    float4 xa = *(const float4*)&xcur[(size_t)n * 64 + li * 4];
    float4 xb = *(const float4*)&xcur[(size_t)n * 64 + 32 + li * 4];
    float den0 = p0, den1 = p1;
    float4 A00 = make_float4(p0 * xa.x, p0 * xa.y, p0 * xa.z, p0 * xa.w);
    float4 A01 = make_float4(p0 * xb.x, p0 * xb.y, p0 * xb.z, p0 * xb.w);
    float4 A10 = make_float4(p1 * xa.x, p1 * xa.y, p1 * xa.z, p1 * xa.w);
    float4 A11 = make_float4(p1 * xb.x, p1 * xb.y, p1 * xb.z, p1 * xb.w);

    int dmax = deg;
#pragma unroll
    for (int o = 16; o; o >>= 1) {
        int y = __shfl_xor_sync(FULLMASK, dmax, o);
        dmax = dmax > y ? dmax : y;
    }
    for (int it = 0; it < dmax; it++) {
        if (it < deg) {
            int src = __ldg(&g_ell[it][seg]);
            float2 e2 = *(const float2*)&g_es[r][src][0];
            float pe0 = __expf(lrelu(e2.x + ed2.x));
            float pe1 = __expf(lrelu(e2.y + ed2.y));
            den0 += pe0; den1 += pe1;
            float4 sa = *(const float4*)&xcur[(size_t)src * 64 + li * 4];
            float4 sb = *(const float4*)&xcur[(size_t)src * 64 + 32 + li * 4];
            A00.x += pe0 * sa.x; A00.y += pe0 * sa.y; A00.z += pe0 * sa.z; A00.w += pe0 * sa.w;
            A01.x += pe0 * sb.x; A01.y += pe0 * sb.y; A01.z += pe0 * sb.z; A01.w += pe0 * sb.w;
            A10.x += pe1 * sa.x; A10.y += pe1 * sa.y; A10.z += pe1 * sa.z; A10.w += pe1 * sa.w;
            A11.x += pe1 * sb.x; A11.y += pe1 * sb.y; A11.z += pe1 * sb.z; A11.w += pe1 * sb.w;
        }
    }
    float i0 = 1.f / den0, i1 = 1.f / den1;
    *(float4*)&g_aggx[r][n][li * 4] =
        make_float4(A00.x * i0, A00.y * i0, A00.z * i0, A00.w * i0);
    *(float4*)&g_aggx[r][n][32 + li * 4] =
        make_float4(A01.x * i0, A01.y * i0, A01.z * i0, A01.w * i0);
    *(float4*)&g_aggx[r][n][64 + li * 4] =
        make_float4(A10.x * i1, A10.y * i1, A10.z * i1, A10.w * i1);
    *(float4*)&g_aggx[r][n][96 + li * 4] =
        make_float4(A11.x * i1, A11.y * i1, A11.z * i1, A11.w * i1);
}

// ================= fused MLP + residual + LayerNorm (FFMA2 v2) =============
constexpr int APAD2 = 132;   // 132*4 = 528 B, 16B-aligned rows
constexpr int BPAD2 = 72;    // 72*4 = 288 B, 16B-aligned rows

__global__ __launch_bounds__(128) void mlp_kernel(
    const float* __restrict__ xin,
    const float* __restrict__ W2, const float* __restrict__ b2,
    const float* __restrict__ lng, const float* __restrict__ lnb,
    float* __restrict__ dout, int layer)
{
    __shared__ float Ast[32 * APAD2];   // 16896 B, [kk][row]
    __shared__ float Bs[32 * BPAD2];    // 9216 B,  [kk][col]
    __shared__ float b1s[64], b2s[64], gs[64], bs2[64];

    int tid = threadIdx.x;
    const float* hin = layer ? &g_hbuf[0][0] : xin;
    float* hout = (layer == L_ - 1) ? dout : &g_hbuf[0][0];

    if (tid < 64) {
        b1s[tid] = g_b1f[layer][tid];
        b2s[tid] = b2[layer * 64 + tid];
        gs[tid]  = lng[layer * 64 + tid];
        bs2[tid] = lnb[layer * 64 + tid];
    }

    int nb = blockIdx.x * 128;
    int lane = tid & 31, warp = tid >> 5;
    int tn = (((lane >> 3) & 3) << 1) | (lane & 1);   // 0..7 col group
    int tmw = (lane >> 1) & 3;
    int tm = warp * 4 + tmw;                           // 0..15 row group
    int rb = tm * 8;
    int cb = tn * 8;

    unsigned long long acc2[8][4];
#pragma unroll
    for (int i = 0; i < 8; i++)
#pragma unroll
        for (int p = 0; p < 4; p++) acc2[i][p] = 0ull;

    const float* W1l = &g_W1f[layer][0][0];

    for (int kt = 0; kt < 18; kt++) {
        const float* src; int stride, off;
        if (kt < 2) { src = hin; stride = 64; off = kt * 32; }
        else {
            int k0 = kt * 32 - 64;
            int rr = k0 >> 7; off = k0 & 127;
            src = &g_aggx[rr][0][0]; stride = 128;
        }
        __syncthreads();
#pragma unroll
        for (int i = 0; i < 8; i++) {
            int slot = tid + i * 128;
            int row = slot >> 3, c4 = (slot & 7) * 4;
            int n = nb + row;
            float4 v = make_float4(0.f, 0.f, 0.f, 0.f);
            if (n < N_) v = *(const float4*)&src[(size_t)n * stride + off + c4];
            Ast[(c4 + 0) * APAD2 + row] = v.x;
            Ast[(c4 + 1) * APAD2 + row] = v.y;
            Ast[(c4 + 2) * APAD2 + row] = v.z;
            Ast[(c4 + 3) * APAD2 + row] = v.w;
        }
#pragma unroll
        for (int i = 0; i < 4; i++) {
            int slot = tid + i * 128;
            int kk = slot >> 4, f4 = (slot & 15) * 4;
            *(float4*)&Bs[kk * BPAD2 + f4] = *(const float4*)&W1l[(kt * 32 + kk) * 64 + f4];
        }
        __syncthreads();
#pragma unroll 4
        for (int kk = 0; kk < 32; kk++) {
            float4 a0 = *(float4*)&Ast[kk * APAD2 + rb];
            float4 a1 = *(float4*)&Ast[kk * APAD2 + rb + 4];
            const unsigned long long* bp = (const unsigned long long*)&Bs[kk * BPAD2 + cb];
            unsigned long long b0 = bp[0], b1r = bp[1], b2r = bp[2], b3 = bp[3];
            unsigned long long ad[8];
            ad[0] = packdup(a0.x); ad[1] = packdup(a0.y);
            ad[2] = packdup(a0.z); ad[3] = packdup(a0.w);
            ad[4] = packdup(a1.x); ad[5] = packdup(a1.y);
            ad[6] = packdup(a1.z); ad[7] = packdup(a1.w);
#pragma unroll
            for (int i = 0; i < 8; i++) {
                ffma2(acc2[i][0], ad[i], b0);
                ffma2(acc2[i][1], ad[i], b1r);
                ffma2(acc2[i][2], ad[i], b2r);
                ffma2(acc2[i][3], ad[i], b3);
            }
        }
    }

    float t[8][8];
#pragma unroll
    for (int i = 0; i < 8; i++)
#pragma unroll
        for (int p = 0; p < 4; p++) {
            float lo = __uint_as_float((unsigned)(acc2[i][p] & 0xffffffffull));
            float hi = __uint_as_float((unsigned)(acc2[i][p] >> 32));
            t[i][2 * p]     = tanhf(lo + b1s[cb + 2 * p]);
            t[i][2 * p + 1] = tanhf(hi + b1s[cb + 2 * p + 1]);
        }

    const float* W2l = W2 + (size_t)layer * 64 * 64;
    unsigned long long z2[8][4];
#pragma unroll
    for (int i = 0; i < 8; i++)
#pragma unroll
        for (int p = 0; p < 4; p++) z2[i][p] = 0ull;

    for (int half = 0; half < 2; half++) {
        __syncthreads();
        if ((tn >> 2) == half) {
            int cl = cb - half * 32;
#pragma unroll
            for (int c = 0; c < 8; c++)
#pragma unroll
                for (int i = 0; i < 8; i++)
                    Ast[(cl + c) * APAD2 + rb + i] = t[i][c];
        }
#pragma unroll
        for (int i = 0; i < 4; i++) {
            int slot = tid + i * 128;
            int kk = slot >> 4, f4 = (slot & 15) * 4;
            *(float4*)&Bs[kk * BPAD2 + f4] = *(const float4*)&W2l[(half * 32 + kk) * 64 + f4];
        }
        __syncthreads();
#pragma unroll 4
        for (int kk = 0; kk < 32; kk++) {
            float4 a0 = *(float4*)&Ast[kk * APAD2 + rb];
            float4 a1 = *(float4*)&Ast[kk * APAD2 + rb + 4];
            const unsigned long long* bp = (const unsigned long long*)&Bs[kk * BPAD2 + cb];
            unsigned long long b0 = bp[0], b1r = bp[1], b2r = bp[2], b3 = bp[3];
            unsigned long long ad[8];
            ad[0] = packdup(a0.x); ad[1] = packdup(a0.y);
            ad[2] = packdup(a0.z); ad[3] = packdup(a0.w);
            ad[4] = packdup(a1.x); ad[5] = packdup(a1.y);
            ad[6] = packdup(a1.z); ad[7] = packdup(a1.w);
#pragma unroll
            for (int i = 0; i < 8; i++) {
                ffma2(z2[i][0], ad[i], b0);
                ffma2(z2[i][1], ad[i], b1r);
                ffma2(z2[i][2], ad[i], b2r);
                ffma2(z2[i][3], ad[i], b3);
            }
        }
    }

#pragma unroll
    for (int i = 0; i < 8; i++) {
        int n = nb + rb + i;
        bool valid = n < N_;
        float4 h0 = make_float4(0.f, 0.f, 0.f, 0.f), h1 = h0;
        if (valid) {
            h0 = *(const float4*)&hin[(size_t)n * 64 + cb];
            h1 = *(const float4*)&hin[(size_t)n * 64 + cb + 4];
        }
        float zz[8];
#pragma unroll
        for (int p = 0; p < 4; p++) {
            zz[2 * p]     = __uint_as_float((unsigned)(z2[i][p] & 0xffffffffull));
            zz[2 * p + 1] = __uint_as_float((unsigned)(z2[i][p] >> 32));
        }
        zz[0] += b2s[cb + 0] + h0.x; zz[1] += b2s[cb + 1] + h0.y;
        zz[2] += b2s[cb + 2] + h0.z; zz[3] += b2s[cb + 3] + h0.w;
        zz[4] += b2s[cb + 4] + h1.x; zz[5] += b2s[cb + 5] + h1.y;
        zz[6] += b2s[cb + 6] + h1.z; zz[7] += b2s[cb + 7] + h1.w;
        float s = 0.f, ss = 0.f;
#pragma unroll
        for (int q = 0; q < 8; q++) { s += zz[q]; ss += zz[q] * zz[q]; }
#pragma unroll
        for (int msk = 0; msk < 3; msk++) {
            int o = (msk == 0) ? 16 : (msk == 1) ? 8 : 1;
            s  += __shfl_xor_sync(FULLMASK, s, o);
            ss += __shfl_xor_sync(FULLMASK, ss, o);
        }
        float mu = s * (1.f / 64.f);
        float var = ss * (1.f / 64.f) - mu * mu;
        float rs = rsqrtf(var + 1e-5f);
        if (valid) {
            float4 o0, o1;
            o0.x = (zz[0] - mu) * rs * gs[cb + 0] + bs2[cb + 0];
            o0.y = (zz[1] - mu) * rs * gs[cb + 1] + bs2[cb + 1];
            o0.z = (zz[2] - mu) * rs * gs[cb + 2] + bs2[cb + 2];
            o0.w = (zz[3] - mu) * rs * gs[cb + 3] + bs2[cb + 3];
            o1.x = (zz[4] - mu) * rs * gs[cb + 4] + bs2[cb + 4];
            o1.y = (zz[5] - mu) * rs * gs[cb + 5] + bs2[cb + 5];
            o1.z = (zz[6] - mu) * rs * gs[cb + 6] + bs2[cb + 6];
            o1.w = (zz[7] - mu) * rs * gs[cb + 7] + bs2[cb + 7];
            *(float4*)&hout[(size_t)n * 64 + cb]     = o0;
            *(float4*)&hout[(size_t)n * 64 + cb + 4] = o1;
        }
    }
}

// ---------------- host launcher --------------------------------------------
extern "C" void kernel_launch(void* const* d_in, const int* in_sizes, int n_in,
                              void* d_out, int out_size)
{
    const float* x    = (const float*)d_in[0];
    const int*   ei   = (const int*)d_in[1];
    const float* ew   = (const float*)d_in[2];
    const float* gatW = (const float*)d_in[3];
    const float* asrc = (const float*)d_in[4];
    const float* adst = (const float*)d_in[5];
    const float* gbias= (const float*)d_in[6];
    const float* W1   = (const float*)d_in[7];
    const float* b1   = (const float*)d_in[8];
    const float* W2   = (const float*)d_in[9];
    const float* b2   = (const float*)d_in[10];
    const float* lng  = (const float*)d_in[11];
    const float* lnb  = (const float*)d_in[12];
    float* out = (float*)d_out;

    int aggblk = (SEG_ / 4 * 32 + 255) / 256;   // 6250

    setup_kernel<<<L_ + 17 + (SEG_ / 4 + 255) / 256, 256>>>(gatW, asrc, adst, W1, b1, gbias); // 0
    ell_build_kernel<<<(E_ + 255) / 256, 256>>>(ei, ew);                   // 1
    logits_kernel<<<(N_ + 63) / 64, 256>>>(x, 0);                          // 2
    agg_kernel<<<aggblk, 256>>>(x, 0);                                     // 3  <- profiled
    mlp_kernel<<<(N_ + 127) / 128, 128>>>(x, W2, b2, lng, lnb, out, 0);    // 4
    logits_kernel<<<(N_ + 63) / 64, 256>>>(x, 1);                          // 5
    agg_kernel<<<aggblk, 256>>>(x, 1);                                     // 6
    mlp_kernel<<<(N_ + 127) / 128, 128>>>(x, W2, b2, lng, lnb, out, 1);    // 7
}

// round 13
// speedup vs baseline: 1.0002x; 1.0002x over previous
#include <cuda_runtime.h>
#include <math.h>

#define FULLMASK 0xffffffffu

constexpr int N_ = 50000;
constexpr int E_ = 400000;
constexpr int R_ = 4;
constexpr int HC_ = 128;   // H*C
constexpr int D_ = 64;     // IN == HID
constexpr int L_ = 2;
constexpr int K1_ = D_ + R_ * HC_;  // 576
constexpr int SEG_ = R_ * N_;       // 200000 segments
constexpr int CAP_ = 32;            // ELL capacity (deg ~ Poisson(4); P(>=32) ~ 1e-19)
constexpr int LOGITS_BLKS = (N_ + 63) / 64;        // 782
constexpr int ELL_BLKS = (E_ + 255) / 256;         // 1563

// ---------------- scratch (device globals) ---------------------------------
__device__ int g_ellcnt[SEG_];          // zero-init at load; re-zeroed by setup
__device__ int g_ell[CAP_][SEG_];       // transposed ELL adjacency

__device__ float g_es[R_][N_][2];       // per-node source logits, per head
__device__ float g_ed[R_][N_][2];       // per-node dest logits, per head
__device__ float g_aggx[R_][N_][HC_];   // normalized alpha-weighted x, [h*64+k]
__device__ float g_hbuf[N_][D_];        // inter-layer features
__device__ float g_va[L_][2][R_][2][D_];  // folded W@a_{src,dst}
__device__ float g_W1f[L_][K1_][D_];    // MLP W1 with GAT W folded in
__device__ float g_b1f[L_][D_];         // b1 with gat_bias folded in

__device__ __forceinline__ float lrelu(float x) { return x > 0.f ? x : 0.2f * x; }

// packed 2xfp32 FMA (sm_100+): d = a*b + d elementwise on {lo,hi}
__device__ __forceinline__ void ffma2(unsigned long long& d,
                                      unsigned long long a, unsigned long long b) {
    asm("fma.rn.f32x2 %0, %1, %2, %3;" : "=l"(d) : "l"(a), "l"(b), "l"(d));
}
// duplicate a float into both halves of a packed f32x2
__device__ __forceinline__ unsigned long long packdup(float a) {
    unsigned long long d;
    unsigned int u = __float_as_uint(a);
    asm("mov.b64 %0, {%1, %1};" : "=l"(d) : "r"(u));
    return d;
}

// ================= merged one-time setup ====================================
__global__ __launch_bounds__(256) void setup_kernel(
    const float* __restrict__ gatW, const float* __restrict__ asrc,
    const float* __restrict__ adst, const float* __restrict__ W1,
    const float* __restrict__ b1, const float* __restrict__ gbias)
{
    __shared__ float Wt[64][65];   // [k][c]
    __shared__ float W1t[64][64];  // [c][j]
    int b = blockIdx.x;
    int tid = threadIdx.x;

    if (b == 0) {
#pragma unroll
        for (int it = 0; it < 4; it++) {
            int t = tid + it * 256;
            int k = t & 63;
            int h = (t >> 6) & 1;
            int r = (t >> 7) & 3;
            int l = t >> 9;
            const float* Wrow = gatW + (((size_t)(l * R_ + r) * 64 + k) * 128) + h * 64;
            const float* as = asrc + ((l * R_ + r) * 2 + h) * 64;
            const float* ad = adst + ((l * R_ + r) * 2 + h) * 64;
            float ss = 0.f, ds = 0.f;
#pragma unroll 16
            for (int c = 0; c < 64; c++) { ss += Wrow[c] * as[c]; ds += Wrow[c] * ad[c]; }
            g_va[l][0][r][h][k] = ss;
            g_va[l][1][r][h][k] = ds;
        }
    } else if (b <= L_) {
        int l = b - 1;
        for (int i = tid; i < 64 * 64 / 4; i += 256)
            ((float4*)&g_W1f[l][0][0])[i] = ((const float4*)&W1[(size_t)l * K1_ * 64])[i];
        if (tid < 64) {
            float bb = b1[l * 64 + tid];
            for (int row = 0; row < 512; row++) {
                int r = row >> 7, idx = row & 127;
                bb += gbias[(l * R_ + r) * HC_ + idx] *
                      W1[((size_t)l * K1_ + 64 + row) * 64 + tid];
            }
            g_b1f[l][tid] = bb;
        }
    } else if (b <= L_ + 16) {
        int sub = b - 3;
        int l = sub >> 3, r = (sub >> 1) & 3, h = sub & 1;
#pragma unroll
        for (int i = 0; i < 4; i++) {
            int s = tid + i * 256;
            int k = s >> 4, c4 = (s & 15) * 4;
            float4 wv = *(const float4*)&gatW[((size_t)(l * R_ + r) * 64 + k) * 128 + h * 64 + c4];
            Wt[k][c4] = wv.x; Wt[k][c4 + 1] = wv.y; Wt[k][c4 + 2] = wv.z; Wt[k][c4 + 3] = wv.w;
            int c = s >> 4, j4 = (s & 15) * 4;
            *(float4*)&W1t[c][j4] =
                *(const float4*)&W1[((size_t)l * K1_ + 64 + r * 128 + h * 64 + c) * 64 + j4];
        }
        __syncthreads();
        int j4 = (tid & 15) * 4;
        int kb = tid >> 4;
#pragma unroll
        for (int kk = 0; kk < 4; kk++) {
            int k = kb + kk * 16;
            float a0 = 0.f, a1 = 0.f, a2 = 0.f, a3 = 0.f;
#pragma unroll 16
            for (int c = 0; c < 64; c++) {
                float a = Wt[k][c];
                float4 wv = *(float4*)&W1t[c][j4];
                a0 += a * wv.x; a1 += a * wv.y; a2 += a * wv.z; a3 += a * wv.w;
            }
            *(float4*)&g_W1f[l][64 + r * 128 + h * 64 + k][j4] = make_float4(a0, a1, a2, a3);
        }
    } else {
        int i4 = (b - (L_ + 17)) * 256 + tid;
        if (i4 < SEG_ / 4) ((int4*)g_ellcnt)[i4] = make_int4(0, 0, 0, 0);
    }
}

// ================= logits body (device fn, shared by fused + standalone) ===
__device__ __forceinline__ void logits_body(const float* __restrict__ xcur,
                                            int layer, int blk)
{
    __shared__ float xs[64][68];    // stride 68: 16B-aligned float4 rows
    __shared__ float vas[16][68];
    int tid = threadIdx.x;
    int nb = blk * 64;
#pragma unroll
    for (int i = 0; i < 4; i++) {
        int s = tid + i * 256;
        int row = s >> 4, c4 = (s & 15) * 4;
        int n = nb + row;
        float4 v = (n < N_) ? *(const float4*)&xcur[(size_t)n * 64 + c4]
                            : make_float4(0.f, 0.f, 0.f, 0.f);
        xs[row][c4] = v.x; xs[row][c4 + 1] = v.y; xs[row][c4 + 2] = v.z; xs[row][c4 + 3] = v.w;
    }
    {
        int o = tid >> 4, c4 = (tid & 15) * 4;
        int which = o >> 3, oo = o & 7;
        int r = oo >> 1, h = oo & 1;
        float4 v = *(const float4*)&g_va[layer][which][r][h][c4];
        vas[o][c4] = v.x; vas[o][c4 + 1] = v.y; vas[o][c4 + 2] = v.z; vas[o][c4 + 3] = v.w;
    }
    __syncthreads();

    int o = tid & 15;
    int n0 = tid >> 4;
    float s0 = 0.f, s1 = 0.f, s2 = 0.f, s3 = 0.f;
#pragma unroll
    for (int k4 = 0; k4 < 64; k4 += 4) {
        float4 va = *(float4*)&vas[o][k4];
        float4 a = *(float4*)&xs[n0][k4];
        float4 b = *(float4*)&xs[n0 + 16][k4];
        float4 c = *(float4*)&xs[n0 + 32][k4];
        float4 d = *(float4*)&xs[n0 + 48][k4];
        s0 += a.x * va.x + a.y * va.y + a.z * va.z + a.w * va.w;
        s1 += b.x * va.x + b.y * va.y + b.z * va.z + b.w * va.w;
        s2 += c.x * va.x + c.y * va.y + c.z * va.z + c.w * va.w;
        s3 += d.x * va.x + d.y * va.y + d.z * va.z + d.w * va.w;
    }
    int which = o >> 3, oo = o & 7;
    int r = oo >> 1, h = oo & 1;
    float sv[4] = {s0, s1, s2, s3};
#pragma unroll
    for (int i = 0; i < 4; i++) {
        int n = nb + n0 + i * 16;
        if (n < N_) {
            if (which == 0) g_es[r][n][h] = sv[i];
            else            g_ed[r][n][h] = sv[i];
        }
    }
}

// ================= fused: logits layer 0 + ELL build =======================
__global__ __launch_bounds__(256) void logits_ell_kernel(
    const float* __restrict__ x, const int* __restrict__ ei,
    const float* __restrict__ ew)
{
    if (blockIdx.x < LOGITS_BLKS) {
        logits_body(x, 0, blockIdx.x);
    } else {
        int e = (blockIdx.x - LOGITS_BLKS) * 256 + threadIdx.x;
        if (e >= E_) return;
        float w = ew[e];
        if (w == 0.f) return;
        int s = ei[e], d = ei[E_ + e];
        int rf = (w > 0.f) ? 0 : 2;
        int seg0 = rf * N_ + d;
        int p0 = atomicAdd(&g_ellcnt[seg0], 1);
        if (p0 < CAP_) g_ell[p0][seg0] = s;
        int seg1 = (rf + 1) * N_ + s;
        int p1 = atomicAdd(&g_ellcnt[seg1], 1);
        if (p1 < CAP_) g_ell[p1][seg1] = d;
    }
}

// standalone logits for layer 1
__global__ __launch_bounds__(256) void logits_kernel(int layer)
{
    logits_body(&g_hbuf[0][0], layer, blockIdx.x);
}

// ================= per-layer: ELL softmax-aggregate (v5) ===================
// 2 segments per warp, 16 lanes per segment; branch-free predicated body
// (slot clamped to 0, contribution masked) so the compiler software-pipelines
// 4 independent gather chains per unrolled group.
__global__ __launch_bounds__(256) void agg_kernel(const float* __restrict__ xin, int layer)
{
    const float* xcur = layer ? &g_hbuf[0][0] : xin;
    int warp = (blockIdx.x * 256 + threadIdx.x) >> 5;
    int lane = threadIdx.x & 31;
    int li = lane & 15;
    int seg = warp * 2 + (lane >> 4);   // SEG_ % 2 == 0
    if (seg >= SEG_) return;
    int r = seg / N_;
    int n = seg - r * N_;

    int deg = __ldg(&g_ellcnt[seg]);
    deg = deg < CAP_ ? deg : CAP_;

    float2 ed2 = *(const float2*)&g_ed[r][n][0];
    float2 es2 = *(const float2*)&g_es[r][n][0];
    float p0 = __expf(lrelu(es2.x + ed2.x));   // self loop, head 0
    float p1 = __expf(lrelu(es2.y + ed2.y));   // self loop, head 1
    float4 xv = *(const float4*)&xcur[(size_t)n * 64 + li * 4];
    float den0 = p0, den1 = p1;
    float4 A0 = make_float4(p0 * xv.x, p0 * xv.y, p0 * xv.z, p0 * xv.w);
    float4 A1 = make_float4(p1 * xv.x, p1 * xv.y, p1 * xv.z, p1 * xv.w);

    int dmax = deg;
#pragma unroll
    for (int o = 16; o; o >>= 1) {
        int y = __shfl_xor_sync(FULLMASK, dmax, o);
        dmax = dmax > y ? dmax : y;
    }
#pragma unroll 4
    for (int it = 0; it < dmax; it++) {
        int slot = it < deg ? it : 0;          // slot 0 always valid (masked)
        float msk = it < deg ? 1.f : 0.f;
        int src = __ldg(&g_ell[slot][seg]);
        float2 e2 = *(const float2*)&g_es[r][src][0];
        float pe0 = msk * __expf(lrelu(e2.x + ed2.x));
        float pe1 = msk * __expf(lrelu(e2.y + ed2.y));
        den0 += pe0; den1 += pe1;
        float4 sv = *(const float4*)&xcur[(size_t)src * 64 + li * 4];
        A0.x += pe0 * sv.x; A0.y += pe0 * sv.y; A0.z += pe0 * sv.z; A0.w += pe0 * sv.w;
        A1.x += pe1 * sv.x; A1.y += pe1 * sv.y; A1.z += pe1 * sv.z; A1.w += pe1 * sv.w;
    }
    float i0 = 1.f / den0, i1 = 1.f / den1;
    *(float4*)&g_aggx[r][n][li * 4] =
        make_float4(A0.x * i0, A0.y * i0, A0.z * i0, A0.w * i0);
    *(float4*)&g_aggx[r][n][64 + li * 4] =
        make_float4(A1.x * i1, A1.y * i1, A1.z * i1, A1.w * i1);
}

// ================= fused MLP + residual + LayerNorm (FFMA2 v2) =============
constexpr int APAD2 = 132;   // 132*4 = 528 B, 16B-aligned rows
constexpr int BPAD2 = 72;    // 72*4 = 288 B, 16B-aligned rows

__global__ __launch_bounds__(128) void mlp_kernel(
    const float* __restrict__ xin,
    const float* __restrict__ W2, const float* __restrict__ b2,
    const float* __restrict__ lng, const float* __restrict__ lnb,
    float* __restrict__ dout, int layer)
{
    __shared__ float Ast[32 * APAD2];   // 16896 B, [kk][row]
    __shared__ float Bs[32 * BPAD2];    // 9216 B,  [kk][col]
    __shared__ float b1s[64], b2s[64], gs[64], bs2[64];

    int tid = threadIdx.x;
    const float* hin = layer ? &g_hbuf[0][0] : xin;
    float* hout = (layer == L_ - 1) ? dout : &g_hbuf[0][0];

    if (tid < 64) {
        b1s[tid] = g_b1f[layer][tid];
        b2s[tid] = b2[layer * 64 + tid];
        gs[tid]  = lng[layer * 64 + tid];
        bs2[tid] = lnb[layer * 64 + tid];
    }

    int nb = blockIdx.x * 128;
    int lane = tid & 31, warp = tid >> 5;
    int tn = (((lane >> 3) & 3) << 1) | (lane & 1);   // 0..7 col group
    int tmw = (lane >> 1) & 3;
    int tm = warp * 4 + tmw;                           // 0..15 row group
    int rb = tm * 8;
    int cb = tn * 8;

    unsigned long long acc2[8][4];
#pragma unroll
    for (int i = 0; i < 8; i++)
#pragma unroll
        for (int p = 0; p < 4; p++) acc2[i][p] = 0ull;

    const float* W1l = &g_W1f[layer][0][0];

    for (int kt = 0; kt < 18; kt++) {
        const float* src; int stride, off;
        if (kt < 2) { src = hin; stride = 64; off = kt * 32; }
        else {
            int k0 = kt * 32 - 64;
            int rr = k0 >> 7; off = k0 & 127;
            src = &g_aggx[rr][0][0]; stride = 128;
        }
        __syncthreads();
#pragma unroll
        for (int i = 0; i < 8; i++) {
            int slot = tid + i * 128;
            int row = slot >> 3, c4 = (slot & 7) * 4;
            int n = nb + row;
            float4 v = make_float4(0.f, 0.f, 0.f, 0.f);
            if (n < N_) v = *(const float4*)&src[(size_t)n * stride + off + c4];
            Ast[(c4 + 0) * APAD2 + row] = v.x;
            Ast[(c4 + 1) * APAD2 + row] = v.y;
            Ast[(c4 + 2) * APAD2 + row] = v.z;
            Ast[(c4 + 3) * APAD2 + row] = v.w;
        }
#pragma unroll
        for (int i = 0; i < 4; i++) {
            int slot = tid + i * 128;
            int kk = slot >> 4, f4 = (slot & 15) * 4;
            *(float4*)&Bs[kk * BPAD2 + f4] = *(const float4*)&W1l[(kt * 32 + kk) * 64 + f4];
        }
        __syncthreads();
#pragma unroll 4
        for (int kk = 0; kk < 32; kk++) {
            float4 a0 = *(float4*)&Ast[kk * APAD2 + rb];
            float4 a1 = *(float4*)&Ast[kk * APAD2 + rb + 4];
            const unsigned long long* bp = (const unsigned long long*)&Bs[kk * BPAD2 + cb];
            unsigned long long b0 = bp[0], b1r = bp[1], b2r = bp[2], b3 = bp[3];
            unsigned long long ad[8];
            ad[0] = packdup(a0.x); ad[1] = packdup(a0.y);
            ad[2] = packdup(a0.z); ad[3] = packdup(a0.w);
            ad[4] = packdup(a1.x); ad[5] = packdup(a1.y);
            ad[6] = packdup(a1.z); ad[7] = packdup(a1.w);
#pragma unroll
            for (int i = 0; i < 8; i++) {
                ffma2(acc2[i][0], ad[i], b0);
                ffma2(acc2[i][1], ad[i], b1r);
                ffma2(acc2[i][2], ad[i], b2r);
                ffma2(acc2[i][3], ad[i], b3);
            }
        }
    }

    float t[8][8];
#pragma unroll
    for (int i = 0; i < 8; i++)
#pragma unroll
        for (int p = 0; p < 4; p++) {
            float lo = __uint_as_float((unsigned)(acc2[i][p] & 0xffffffffull));
            float hi = __uint_as_float((unsigned)(acc2[i][p] >> 32));
            t[i][2 * p]     = tanhf(lo + b1s[cb + 2 * p]);
            t[i][2 * p + 1] = tanhf(hi + b1s[cb + 2 * p + 1]);
        }

    const float* W2l = W2 + (size_t)layer * 64 * 64;
    unsigned long long z2[8][4];
#pragma unroll
    for (int i = 0; i < 8; i++)
#pragma unroll
        for (int p = 0; p < 4; p++) z2[i][p] = 0ull;

    for (int half = 0; half < 2; half++) {
        __syncthreads();
        if ((tn >> 2) == half) {
            int cl = cb - half * 32;
#pragma unroll
            for (int c = 0; c < 8; c++)
#pragma unroll
                for (int i = 0; i < 8; i++)
                    Ast[(cl + c) * APAD2 + rb + i] = t[i][c];
        }
#pragma unroll
        for (int i = 0; i < 4; i++) {
            int slot = tid + i * 128;
            int kk = slot >> 4, f4 = (slot & 15) * 4;
            *(float4*)&Bs[kk * BPAD2 + f4] = *(const float4*)&W2l[(half * 32 + kk) * 64 + f4];
        }
        __syncthreads();
#pragma unroll 4
        for (int kk = 0; kk < 32; kk++) {
            float4 a0 = *(float4*)&Ast[kk * APAD2 + rb];
            float4 a1 = *(float4*)&Ast[kk * APAD2 + rb + 4];
            const unsigned long long* bp = (const unsigned long long*)&Bs[kk * BPAD2 + cb];
            unsigned long long b0 = bp[0], b1r = bp[1], b2r = bp[2], b3 = bp[3];
            unsigned long long ad[8];
            ad[0] = packdup(a0.x); ad[1] = packdup(a0.y);
            ad[2] = packdup(a0.z); ad[3] = packdup(a0.w);
            ad[4] = packdup(a1.x); ad[5] = packdup(a1.y);
            ad[6] = packdup(a1.z); ad[7] = packdup(a1.w);
#pragma unroll
            for (int i = 0; i < 8; i++) {
                ffma2(z2[i][0], ad[i], b0);
                ffma2(z2[i][1], ad[i], b1r);
                ffma2(z2[i][2], ad[i], b2r);
                ffma2(z2[i][3], ad[i], b3);
            }
        }
    }

#pragma unroll
    for (int i = 0; i < 8; i++) {
        int n = nb + rb + i;
        bool valid = n < N_;
        float4 h0 = make_float4(0.f, 0.f, 0.f, 0.f), h1 = h0;
        if (valid) {
            h0 = *(const float4*)&hin[(size_t)n * 64 + cb];
            h1 = *(const float4*)&hin[(size_t)n * 64 + cb + 4];
        }
        float zz[8];
#pragma unroll
        for (int p = 0; p < 4; p++) {
            zz[2 * p]     = __uint_as_float((unsigned)(z2[i][p] & 0xffffffffull));
            zz[2 * p + 1] = __uint_as_float((unsigned)(z2[i][p] >> 32));
        }
        zz[0] += b2s[cb + 0] + h0.x; zz[1] += b2s[cb + 1] + h0.y;
        zz[2] += b2s[cb + 2] + h0.z; zz[3] += b2s[cb + 3] + h0.w;
        zz[4] += b2s[cb + 4] + h1.x; zz[5] += b2s[cb + 5] + h1.y;
        zz[6] += b2s[cb + 6] + h1.z; zz[7] += b2s[cb + 7] + h1.w;
        float s = 0.f, ss = 0.f;
#pragma unroll
        for (int q = 0; q < 8; q++) { s += zz[q]; ss += zz[q] * zz[q]; }
#pragma unroll
        for (int msk = 0; msk < 3; msk++) {
            int o = (msk == 0) ? 16 : (msk == 1) ? 8 : 1;
            s  += __shfl_xor_sync(FULLMASK, s, o);
            ss += __shfl_xor_sync(FULLMASK, ss, o);
        }
        float mu = s * (1.f / 64.f);
        float var = ss * (1.f / 64.f) - mu * mu;
        float rs = rsqrtf(var + 1e-5f);
        if (valid) {
            float4 o0, o1;
            o0.x = (zz[0] - mu) * rs * gs[cb + 0] + bs2[cb + 0];
            o0.y = (zz[1] - mu) * rs * gs[cb + 1] + bs2[cb + 1];
            o0.z = (zz[2] - mu) * rs * gs[cb + 2] + bs2[cb + 2];
            o0.w = (zz[3] - mu) * rs * gs[cb + 3] + bs2[cb + 3];
            o1.x = (zz[4] - mu) * rs * gs[cb + 4] + bs2[cb + 4];
            o1.y = (zz[5] - mu) * rs * gs[cb + 5] + bs2[cb + 5];
            o1.z = (zz[6] - mu) * rs * gs[cb + 6] + bs2[cb + 6];
            o1.w = (zz[7] - mu) * rs * gs[cb + 7] + bs2[cb + 7];
            *(float4*)&hout[(size_t)n * 64 + cb]     = o0;
            *(float4*)&hout[(size_t)n * 64 + cb + 4] = o1;
        }
    }
}

// ---------------- host launcher --------------------------------------------
extern "C" void kernel_launch(void* const* d_in, const int* in_sizes, int n_in,
                              void* d_out, int out_size)
{
    const float* x    = (const float*)d_in[0];
    const int*   ei   = (const int*)d_in[1];
    const float* ew   = (const float*)d_in[2];
    const float* gatW = (const float*)d_in[3];
    const float* asrc = (const float*)d_in[4];
    const float* adst = (const float*)d_in[5];
    const float* gbias= (const float*)d_in[6];
    const float* W1   = (const float*)d_in[7];
    const float* b1   = (const float*)d_in[8];
    const float* W2   = (const float*)d_in[9];
    const float* b2   = (const float*)d_in[10];
    const float* lng  = (const float*)d_in[11];
    const float* lnb  = (const float*)d_in[12];
    float* out = (float*)d_out;

    int aggblk = (SEG_ / 2 * 32 + 255) / 256;   // 12500

    setup_kernel<<<L_ + 17 + (SEG_ / 4 + 255) / 256, 256>>>(gatW, asrc, adst, W1, b1, gbias); // 0
    logits_ell_kernel<<<LOGITS_BLKS + ELL_BLKS, 256>>>(x, ei, ew);         // 1
    agg_kernel<<<aggblk, 256>>>(x, 0);                                     // 2
    mlp_kernel<<<(N_ + 127) / 128, 128>>>(x, W2, b2, lng, lnb, out, 0);    // 3  <- profiled
    logits_kernel<<<LOGITS_BLKS, 256>>>(1);                                // 4
    agg_kernel<<<aggblk, 256>>>(x, 1);                                     // 5
    mlp_kernel<<<(N_ + 127) / 128, 128>>>(x, W2, b2, lng, lnb, out, 1);    // 6
}